// round 1
// baseline (speedup 1.0000x reference)
#include <cuda_runtime.h>
#include <cstdint>

#define DD 1024
#define MM 256
#define BBATCH 2048
#define D_CHK 16
#define XSS 20   // xs row stride in floats (16 data + 4 pad; keeps 16B alignment)
#define CSS 9    // cs row stride in float4 (8 data + 1 pad; 144B stride -> conflict-free LDS.128)

typedef unsigned long long ull;

// Scratch (device globals: no allocations allowed)
__device__ float4 g_cq[MM * (DD / 2)];   // per m: 512 quads {4*c1_d, 4*c1_{d+1}, 4*c0_d, 4*c0_{d+1}}
__device__ float  g_logw[MM];
__device__ float  g_comp[BBATCH * MM];   // log2-domain partial sums (pre logw / pre scale-correction)

struct __align__(16) u64x2 { ull lo, hi; };

__device__ __forceinline__ ull ffma2(ull a, ull b, ull c) {
    ull d;
    asm("fma.rn.f32x2 %0, %1, %2, %3;" : "=l"(d) : "l"(a), "l"(b), "l"(c));
    return d;
}
__device__ __forceinline__ ull fmul2(ull a, ull b) {
    ull d;
    asm("mul.rn.f32x2 %0, %1, %2;" : "=l"(d) : "l"(a), "l"(b));
    return d;
}
__device__ __forceinline__ void cp16(uint32_t dst, const void* src) {
    asm volatile("cp.async.ca.shared.global [%0], [%1], 16;" :: "r"(dst), "l"(src));
}

// ---------------------------------------------------------------------------
// Prep: c1' = 4*tanh(P/2) = 4*(2p-1), c0' = 4/(1+exp(P)) = 4*(1-p)
// ---------------------------------------------------------------------------
__global__ void prep_kernel(const float* __restrict__ P) {
    int idx = blockIdx.x * blockDim.x + threadIdx.x;
    if (idx >= MM * (DD / 2)) return;
    int m = idx / (DD / 2), dp = idx % (DD / 2);
    float t0 = P[m * DD + 2 * dp + 0];
    float t1 = P[m * DD + 2 * dp + 1];
    float4 q;
    q.x = 4.0f * tanhf(0.5f * t0);
    q.y = 4.0f * tanhf(0.5f * t1);
    q.z = 4.0f / (1.0f + expf(t0));
    q.w = 4.0f / (1.0f + expf(t1));
    g_cq[idx] = q;
}

// ---------------------------------------------------------------------------
// logw = W - logsumexp(W)
// ---------------------------------------------------------------------------
__global__ void logw_kernel(const float* __restrict__ W) {
    __shared__ float sh[MM];
    int t = threadIdx.x;
    float w = W[t];
    sh[t] = w;
    __syncthreads();
    for (int s = MM / 2; s > 0; s >>= 1) {
        if (t < s) sh[t] = fmaxf(sh[t], sh[t + s]);
        __syncthreads();
    }
    float mx = sh[0];
    __syncthreads();
    sh[t] = expf(w - mx);
    __syncthreads();
    for (int s = MM / 2; s > 0; s >>= 1) {
        if (t < s) sh[t] += sh[t + s];
        __syncthreads();
    }
    g_logw[t] = w - (mx + logf(sh[0]));
}

// ---------------------------------------------------------------------------
// Main: block tile 64 batches x 64 components, 256 threads (16 m-groups x 16
// b-groups), thread tile 4b x 4m, d streamed in 16-wide double-buffered smem
// chunks (cp.async). Inner math is packed f32x2: one FFMA2 + one FMUL2 per
// d-pair per (b,m). Running product merged via __log2f every 32 d.
// ---------------------------------------------------------------------------
__global__ void __launch_bounds__(256, 1) main_kernel(const float* __restrict__ x) {
    __shared__ __align__(16) float  xs[2][64 * XSS];
    __shared__ __align__(16) float4 cs[2][64 * CSS];

    const int t  = threadIdx.x;
    const int tx = t & 15;        // m group
    const int ty = t >> 4;        // b group
    const int bBase = blockIdx.x * 64;
    const int mBase = blockIdx.y * 64;

    // cp.async source mapping: x chunk = 64 rows x 4 quads, c chunk = 64 rows x 8 quads
    const int xr = t >> 2, xq = t & 3;
    const float* xsrc = x + (size_t)(bBase + xr) * DD + xq * 4;
    const int cr0 = t >> 3,          cq0 = t & 7;
    const int cr1 = (t + 256) >> 3,  cq1 = (t + 256) & 7;
    const float4* csrc0 = g_cq + (size_t)(mBase + cr0) * (DD / 2) + cq0;
    const float4* csrc1 = g_cq + (size_t)(mBase + cr1) * (DD / 2) + cq1;

    uint32_t xdst[2], cdst0[2], cdst1[2];
#pragma unroll
    for (int s = 0; s < 2; s++) {
        xdst[s]  = (uint32_t)__cvta_generic_to_shared(&xs[s][xr * XSS + xq * 4]);
        cdst0[s] = (uint32_t)__cvta_generic_to_shared(&cs[s][cr0 * CSS + cq0]);
        cdst1[s] = (uint32_t)__cvta_generic_to_shared(&cs[s][cr1 * CSS + cq1]);
    }

    // Prologue: chunks 0 and 1
    cp16(xdst[0],  xsrc);
    cp16(cdst0[0], csrc0);
    cp16(cdst1[0], csrc1);
    asm volatile("cp.async.commit_group;");
    cp16(xdst[1],  xsrc + D_CHK);
    cp16(cdst0[1], csrc0 + (D_CHK / 2));
    cp16(cdst1[1], csrc1 + (D_CHK / 2));
    asm volatile("cp.async.commit_group;");

    const ull ONE2 = 0x3F8000003F800000ULL;
    ull   prod[4][4];
    float acc[4][4];
#pragma unroll
    for (int i = 0; i < 4; i++)
#pragma unroll
        for (int j = 0; j < 4; j++) { prod[i][j] = ONE2; acc[i][j] = 0.0f; }

    for (int ck = 0; ck < DD / D_CHK; ck++) {
        asm volatile("cp.async.wait_group 1;");
        __syncthreads();
        const int s = ck & 1;
        const u64x2* xrow = reinterpret_cast<const u64x2*>(xs[s]) + ty * (XSS / 4);
        const u64x2* crow = reinterpret_cast<const u64x2*>(cs[s]) + tx * CSS;
#pragma unroll
        for (int j = 0; j < 4; j++) {              // 2 d-pairs per j, 4 j per chunk
            u64x2 xv[4];
#pragma unroll
            for (int i = 0; i < 4; i++) xv[i] = xrow[i * 16 * (XSS / 4) + j];
#pragma unroll
            for (int jm = 0; jm < 4; jm++) {
                u64x2 ca = crow[jm * 16 * CSS + 2 * j];
                u64x2 cb = crow[jm * 16 * CSS + 2 * j + 1];
#pragma unroll
                for (int i = 0; i < 4; i++) {
                    ull l0 = ffma2(ca.lo, xv[i].lo, ca.hi);   // 4*lik for d, d+1
                    ull l1 = ffma2(cb.lo, xv[i].hi, cb.hi);   // 4*lik for d+2, d+3
                    prod[i][jm] = fmul2(prod[i][jm], fmul2(l0, l1));
                }
            }
        }
        __syncthreads();
        if (ck + 2 < DD / D_CHK) {
            cp16(xdst[s],  xsrc  + (ck + 2) * D_CHK);
            cp16(cdst0[s], csrc0 + (ck + 2) * (D_CHK / 2));
            cp16(cdst1[s], csrc1 + (ck + 2) * (D_CHK / 2));
        }
        asm volatile("cp.async.commit_group;");
        if (ck & 1) {   // merge every 32 d (scaled-by-4 product stays in fp32 range)
#pragma unroll
            for (int i = 0; i < 4; i++)
#pragma unroll
                for (int jm = 0; jm < 4; jm++) {
                    float lo = __uint_as_float((unsigned)(prod[i][jm] & 0xFFFFFFFFu));
                    float hi = __uint_as_float((unsigned)(prod[i][jm] >> 32));
                    acc[i][jm] += __log2f(lo * hi);
                    prod[i][jm] = ONE2;
                }
        }
    }

#pragma unroll
    for (int i = 0; i < 4; i++)
#pragma unroll
        for (int jm = 0; jm < 4; jm++) {
            int b = bBase + ty + 16 * i;
            int m = mBase + tx + 16 * jm;
            g_comp[(size_t)b * MM + m] = acc[i][jm];
        }
}

// ---------------------------------------------------------------------------
// Reduce: per-batch logsumexp over 256 components (one warp per batch).
// comp_ll = ln2 * (acc2 - 2048) + logw   [the -2048 undoes the 4^1024 scale]
// ---------------------------------------------------------------------------
__global__ void reduce_kernel(float* __restrict__ out) {
    const float LN2 = 0.69314718055994531f;
    int warp = threadIdx.x >> 5;
    int lane = threadIdx.x & 31;
    int b = blockIdx.x * 8 + warp;
    float v[8];
    float mx = -1e30f;
#pragma unroll
    for (int k = 0; k < 8; k++) {
        int m = lane + 32 * k;
        float c = (g_comp[(size_t)b * MM + m] - 2048.0f) * LN2 + g_logw[m];
        v[k] = c;
        mx = fmaxf(mx, c);
    }
#pragma unroll
    for (int o = 16; o > 0; o >>= 1) mx = fmaxf(mx, __shfl_xor_sync(0xFFFFFFFFu, mx, o));
    float s = 0.0f;
#pragma unroll
    for (int k = 0; k < 8; k++) s += expf(v[k] - mx);
#pragma unroll
    for (int o = 16; o > 0; o >>= 1) s += __shfl_xor_sync(0xFFFFFFFFu, s, o);
    if (lane == 0) out[b] = mx + logf(s);
}

extern "C" void kernel_launch(void* const* d_in, const int* in_sizes, int n_in,
                              void* d_out, int out_size) {
    // Identify inputs by element count (robust to ordering): x=2048*1024, W=256, P=256*1024
    const float* x = nullptr;
    const float* W = nullptr;
    const float* P = nullptr;
    for (int i = 0; i < n_in; i++) {
        if      (in_sizes[i] == BBATCH * DD) x = (const float*)d_in[i];
        else if (in_sizes[i] == MM)          W = (const float*)d_in[i];
        else if (in_sizes[i] == MM * DD)     P = (const float*)d_in[i];
    }

    prep_kernel<<<(MM * (DD / 2) + 255) / 256, 256>>>(P);
    logw_kernel<<<1, MM>>>(W);
    dim3 grid(BBATCH / 64, MM / 64);
    main_kernel<<<grid, 256>>>(x);
    reduce_kernel<<<BBATCH / 8, 256>>>((float*)d_out);
}

// round 2
// speedup vs baseline: 1.9960x; 1.9960x over previous
#include <cuda_runtime.h>
#include <cuda_bf16.h>
#include <cstdint>
#include <cstring>

#define DD 1024
#define MM 256
#define BBATCH 2048
#define NCHUNK 16   // 16 chunks x 64 d

// Scratch (device globals; no allocation allowed)
__device__ __align__(16) uint32_t g_cb[MM * DD];          // [m][2*dp+{0,1}]: bf16x2 {2*c1 pair, 2*c0 pair}
__device__ __align__(16) uint32_t g_xb[BBATCH * (DD/2)];  // [b][dp]: bf16x2 x pair
__device__ __align__(16) float g_logw[MM];
__device__ __align__(16) float g_comp[BBATCH * MM];       // sum of log2(2*lik) over d

__device__ __forceinline__ __nv_bfloat162 asbf2(uint32_t u) {
    __nv_bfloat162 r; memcpy(&r, &u, 4); return r;
}
__device__ __forceinline__ uint32_t asu32(__nv_bfloat162 b) {
    uint32_t u; memcpy(&u, &b, 4); return u;
}
__device__ __forceinline__ void cp16(uint32_t dst, const void* src) {
    asm volatile("cp.async.ca.shared.global [%0], [%1], 16;" :: "r"(dst), "l"(src));
}

// ---------------------------------------------------------------------------
// x -> bf16 pairs
// ---------------------------------------------------------------------------
__global__ void prep_x_kernel(const float* __restrict__ x) {
    int idx = blockIdx.x * blockDim.x + threadIdx.x;      // one per 4 d; exact grid
    float4 v = reinterpret_cast<const float4*>(x)[idx];
    uint2 w;
    w.x = asu32(__floats2bfloat162_rn(v.x, v.y));
    w.y = asu32(__floats2bfloat162_rn(v.z, v.w));
    reinterpret_cast<uint2*>(g_xb)[idx] = w;
}

// ---------------------------------------------------------------------------
// P -> scaled coefs: c1' = 2*(2p-1), c0' = 2*(1-p), p = sigmoid(P), bf16 pairs
// ---------------------------------------------------------------------------
__global__ void prep_c_kernel(const float* __restrict__ P) {
    int idx = blockIdx.x * blockDim.x + threadIdx.x;      // one per dp (2 d); exact grid
    float2 pv = reinterpret_cast<const float2*>(P)[idx];
    float e0 = __expf(pv.x), e1 = __expf(pv.y);
    float c0a = 2.0f / (1.0f + e0);
    float c0b = 2.0f / (1.0f + e1);
    float c1a = 2.0f - 2.0f * c0a;
    float c1b = 2.0f - 2.0f * c0b;
    uint2 w;
    w.x = asu32(__floats2bfloat162_rn(c1a, c1b));
    w.y = asu32(__floats2bfloat162_rn(c0a, c0b));
    reinterpret_cast<uint2*>(g_cb)[idx] = w;
}

// ---------------------------------------------------------------------------
// logw = W - logsumexp(W)
// ---------------------------------------------------------------------------
__global__ void logw_kernel(const float* __restrict__ W) {
    __shared__ float sh[MM];
    int t = threadIdx.x;
    float w = W[t];
    sh[t] = w;
    __syncthreads();
    for (int s = MM / 2; s > 0; s >>= 1) {
        if (t < s) sh[t] = fmaxf(sh[t], sh[t + s]);
        __syncthreads();
    }
    float mx = sh[0];
    __syncthreads();
    sh[t] = expf(w - mx);
    __syncthreads();
    for (int s = MM / 2; s > 0; s >>= 1) {
        if (t < s) sh[t] += sh[t + s];
        __syncthreads();
    }
    g_logw[t] = w - (mx + logf(sh[0]));
}

// ---------------------------------------------------------------------------
// Main: block 64b x 64m, 256 threads = 16(tx,m) x 8(ty,b) x 2(tz,d-split),
// thread tile 8b x 4m over half of each 64-d chunk. bf16 HFMA2/HMUL2 inner,
// __log2f merge per 32 d. Double-buffered cp.async.
// smem: xs 2*64 rows * 128B (broadcast reads, no pad)
//       cs 2*64 rows * 272B (16 data units + 1 pad -> conflict-free LDS.128)
// ---------------------------------------------------------------------------
__global__ void __launch_bounds__(256, 1) main_kernel() {
    extern __shared__ uint4 sm[];
    uint4* xs = sm;            // [s*512  + row*8  + u]
    uint4* cs = sm + 1024;     // [s*1088 + row*17 + u]

    const int t  = threadIdx.x;
    const int tx = t & 15;
    const int ty = (t >> 4) & 7;
    const int tz = t >> 7;
    const int bBase = blockIdx.x * 64;
    const int mBase = blockIdx.y * 64;

    // cp.async mappings: x = 2 ops/thread (rows xr, xr+32), c = 4 ops/thread
    const int xq = t & 7,  xr = t >> 3;
    const int cq = t & 15, cr = t >> 4;
    const uint32_t* xsrc = g_xb + (size_t)(bBase + xr) * (DD / 2) + xq * 4;
    const uint32_t* csrc = g_cb + (size_t)(mBase + cr) * DD + cq * 4;

    uint32_t xd[2], cd[2];
    xd[0] = (uint32_t)__cvta_generic_to_shared(&xs[xr * 8 + xq]);
    xd[1] = xd[0] + 512 * 16;
    cd[0] = (uint32_t)__cvta_generic_to_shared(&cs[cr * 17 + cq]);
    cd[1] = cd[0] + 1088 * 16;

    auto load_chunk = [&](int ck) {
        int s = ck & 1;
        const uint32_t* xp = xsrc + ck * 32;
        cp16(xd[s], xp);
        cp16(xd[s] + 32 * 8 * 16, xp + 32 * (DD / 2));
        const uint32_t* cp = csrc + ck * 64;
#pragma unroll
        for (int p = 0; p < 4; p++)
            cp16(cd[s] + p * 16 * 17 * 16, cp + p * 16 * DD);
        asm volatile("cp.async.commit_group;");
    };

    load_chunk(0);
    load_chunk(1);

    const uint32_t ONE2 = 0x3F803F80u;   // bf16x2 {1.0, 1.0}
    __nv_bfloat162 prod[8][4];
    float acc[8][4];
#pragma unroll
    for (int i = 0; i < 8; i++)
#pragma unroll
        for (int jm = 0; jm < 4; jm++) { prod[i][jm] = asbf2(ONE2); acc[i][jm] = 0.0f; }

    for (int ck = 0; ck < NCHUNK; ck++) {
        asm volatile("cp.async.wait_group 1;");
        __syncthreads();
        const int s = ck & 1;
        const uint4* xb = xs + s * 512  + ty * 8  + tz * 4;
        const uint4* cb = cs + s * 1088 + tx * 17 + tz * 8;
#pragma unroll
        for (int jq = 0; jq < 4; jq++) {          // 8 d per jq (per tz half)
            uint4 xv[8];
#pragma unroll
            for (int i = 0; i < 8; i++) xv[i] = xb[i * 64 + jq];
#pragma unroll
            for (int jm = 0; jm < 4; jm++) {
                uint4 cu0 = cb[jm * 272 + jq * 2];
                uint4 cu1 = cb[jm * 272 + jq * 2 + 1];
#pragma unroll
                for (int i = 0; i < 8; i++) {
                    __nv_bfloat162 l0 = __hfma2(asbf2(cu0.x), asbf2(xv[i].x), asbf2(cu0.y));
                    __nv_bfloat162 l1 = __hfma2(asbf2(cu0.z), asbf2(xv[i].y), asbf2(cu0.w));
                    __nv_bfloat162 l2 = __hfma2(asbf2(cu1.x), asbf2(xv[i].z), asbf2(cu1.y));
                    __nv_bfloat162 l3 = __hfma2(asbf2(cu1.z), asbf2(xv[i].w), asbf2(cu1.w));
                    __nv_bfloat162 m01 = __hmul2(l0, l1);
                    __nv_bfloat162 m23 = __hmul2(l2, l3);
                    prod[i][jm] = __hmul2(prod[i][jm], __hmul2(m01, m23));
                }
            }
        }
        __syncthreads();
        if (ck + 2 < NCHUNK) load_chunk(ck + 2);
        else asm volatile("cp.async.commit_group;");
        // merge: this chunk contributed 32 d per accumulator (safe exponent range)
#pragma unroll
        for (int i = 0; i < 8; i++)
#pragma unroll
            for (int jm = 0; jm < 4; jm++) {
                uint32_t u = asu32(prod[i][jm]);
                float hi = __uint_as_float(u & 0xFFFF0000u);
                float lo = __uint_as_float(u << 16);
                acc[i][jm] += __log2f(hi * lo);
                prod[i][jm] = asbf2(ONE2);
            }
    }

    asm volatile("cp.async.wait_group 0;");
    __syncthreads();
    // combine tz halves through smem (stride 33 floats to dodge bank conflicts)
    float* sh = (float*)sm;
    const int tid128 = t & 127;
    if (tz == 1) {
#pragma unroll
        for (int i = 0; i < 8; i++)
#pragma unroll
            for (int jm = 0; jm < 4; jm++)
                sh[tid128 * 33 + i * 4 + jm] = acc[i][jm];
    }
    __syncthreads();
    if (tz == 0) {
#pragma unroll
        for (int i = 0; i < 8; i++)
#pragma unroll
            for (int jm = 0; jm < 4; jm++) {
                float a = acc[i][jm] + sh[tid128 * 33 + i * 4 + jm];
                g_comp[(size_t)(bBase + ty + 8 * i) * MM + (mBase + tx + 16 * jm)] = a;
            }
    }
}

// ---------------------------------------------------------------------------
// Reduce: per-batch logsumexp over 256 components (one warp per batch).
// comp_ll = ln2*(acc2 - 1024) + logw   [undoes the 2^1024 scaling]
// ---------------------------------------------------------------------------
__global__ void reduce_kernel(float* __restrict__ out) {
    const float LN2 = 0.69314718055994531f;
    int warp = threadIdx.x >> 5;
    int lane = threadIdx.x & 31;
    int b = blockIdx.x * 8 + warp;
    const float4* cp4 = reinterpret_cast<const float4*>(g_comp + (size_t)b * MM);
    const float4* lw4 = reinterpret_cast<const float4*>(g_logw);
    float v[8];
    float mx = -1e30f;
#pragma unroll
    for (int k = 0; k < 2; k++) {
        float4 c = cp4[lane * 2 + k];
        float4 l = lw4[lane * 2 + k];
        v[k*4+0] = (c.x - 1024.0f) * LN2 + l.x;
        v[k*4+1] = (c.y - 1024.0f) * LN2 + l.y;
        v[k*4+2] = (c.z - 1024.0f) * LN2 + l.z;
        v[k*4+3] = (c.w - 1024.0f) * LN2 + l.w;
#pragma unroll
        for (int j = 0; j < 4; j++) mx = fmaxf(mx, v[k*4+j]);
    }
#pragma unroll
    for (int o = 16; o > 0; o >>= 1) mx = fmaxf(mx, __shfl_xor_sync(0xFFFFFFFFu, mx, o));
    float s = 0.0f;
#pragma unroll
    for (int k = 0; k < 8; k++) s += expf(v[k] - mx);
#pragma unroll
    for (int o = 16; o > 0; o >>= 1) s += __shfl_xor_sync(0xFFFFFFFFu, s, o);
    if (lane == 0) out[b] = mx + logf(s);
}

extern "C" void kernel_launch(void* const* d_in, const int* in_sizes, int n_in,
                              void* d_out, int out_size) {
    const float* x = nullptr;
    const float* W = nullptr;
    const float* P = nullptr;
    for (int i = 0; i < n_in; i++) {
        if      (in_sizes[i] == BBATCH * DD) x = (const float*)d_in[i];
        else if (in_sizes[i] == MM)          W = (const float*)d_in[i];
        else if (in_sizes[i] == MM * DD)     P = (const float*)d_in[i];
    }

    prep_x_kernel<<<(BBATCH * DD / 4) / 256, 256>>>(x);   // 2048 blocks
    prep_c_kernel<<<(MM * DD / 2) / 256, 256>>>(P);       // 512 blocks
    logw_kernel<<<1, MM>>>(W);

    const int SMEM = 1024 * 16 + 2176 * 16;               // 16384 + 34816 = 51200
    cudaFuncSetAttribute(main_kernel, cudaFuncAttributeMaxDynamicSharedMemorySize, SMEM);
    dim3 grid(BBATCH / 64, MM / 64);
    main_kernel<<<grid, 256, SMEM>>>();

    reduce_kernel<<<BBATCH / 8, 256>>>((float*)d_out);
}

// round 3
// speedup vs baseline: 2.1136x; 1.0589x over previous
#include <cuda_runtime.h>
#include <cuda_bf16.h>
#include <cstdint>
#include <cstring>

#define DD 1024
#define MM 256
#define BBATCH 2048
#define NCHUNK 16   // 16 chunks x 64 d

// Scratch (device globals; no allocation allowed)
__device__ __align__(16) uint32_t g_cb[MM * DD];          // [m][2*dp+{0,1}]: bf16x2 {2*c1 pair, 2*c0 pair}
__device__ __align__(16) uint32_t g_xb[BBATCH * (DD/2)];  // [b][dp]: bf16x2 x pair
__device__ __align__(16) float g_logw[MM];
__device__ __align__(16) float g_comp[BBATCH * MM];       // sum of log2(2*lik) over d

__device__ __forceinline__ __nv_bfloat162 asbf2(uint32_t u) {
    __nv_bfloat162 r; memcpy(&r, &u, 4); return r;
}
__device__ __forceinline__ uint32_t asu32(__nv_bfloat162 b) {
    uint32_t u; memcpy(&u, &b, 4); return u;
}
__device__ __forceinline__ void cp16(uint32_t dst, const void* src) {
    asm volatile("cp.async.ca.shared.global [%0], [%1], 16;" :: "r"(dst), "l"(src));
}

// ---------------------------------------------------------------------------
// Fused prep: blocks [0,2048) convert x -> bf16 pairs;
//             blocks [2048,2560) convert P -> scaled coefs;
//             block 2560 computes logw = W - logsumexp(W).
// ---------------------------------------------------------------------------
__global__ void prep_kernel(const float* __restrict__ x,
                            const float* __restrict__ P,
                            const float* __restrict__ W) {
    int bk = blockIdx.x;
    int tid = threadIdx.x;
    if (bk < 2048) {
        int idx = bk * 256 + tid;                 // one per 4 d of x
        float4 v = reinterpret_cast<const float4*>(x)[idx];
        uint2 w;
        w.x = asu32(__floats2bfloat162_rn(v.x, v.y));
        w.y = asu32(__floats2bfloat162_rn(v.z, v.w));
        reinterpret_cast<uint2*>(g_xb)[idx] = w;
    } else if (bk < 2560) {
        int idx = (bk - 2048) * 256 + tid;        // one per d-pair of P
        float2 pv = reinterpret_cast<const float2*>(P)[idx];
        float c0a = 2.0f / (1.0f + __expf(pv.x)); // 2*(1-p)
        float c0b = 2.0f / (1.0f + __expf(pv.y));
        float c1a = 2.0f - 2.0f * c0a;            // 2*(2p-1)
        float c1b = 2.0f - 2.0f * c0b;
        uint2 w;
        w.x = asu32(__floats2bfloat162_rn(c1a, c1b));
        w.y = asu32(__floats2bfloat162_rn(c0a, c0b));
        reinterpret_cast<uint2*>(g_cb)[idx] = w;
    } else {
        __shared__ float sh[MM];
        float w = W[tid];
        sh[tid] = w;
        __syncthreads();
        for (int s = MM / 2; s > 0; s >>= 1) {
            if (tid < s) sh[tid] = fmaxf(sh[tid], sh[tid + s]);
            __syncthreads();
        }
        float mx = sh[0];
        __syncthreads();
        sh[tid] = expf(w - mx);
        __syncthreads();
        for (int s = MM / 2; s > 0; s >>= 1) {
            if (tid < s) sh[tid] += sh[tid + s];
            __syncthreads();
        }
        g_logw[tid] = w - (mx + logf(sh[0]));
    }
}

// ---------------------------------------------------------------------------
// Main: block 64b x 64m, 512 threads = 16(tx,m) x 16(ty,b) x 2(tz,d-split),
// thread tile 4b x 4m over half of each 64-d chunk. bf16 HFMA2/HMUL2 inner,
// __log2f merge per 32 d. Double-buffered cp.async.
// smem: xs 2 x 64 rows x 128B (8 uint4/row, broadcast reads, no pad)
//       cs 2 x 64 rows x 272B (16 data uint4 + 1 pad -> conflict-free LDS.128)
// ---------------------------------------------------------------------------
__global__ void __launch_bounds__(512, 1) main_kernel() {
    extern __shared__ uint4 sm[];
    uint4* xs = sm;            // [s*512  + row*8  + u]
    uint4* cs = sm + 1024;     // [s*1088 + row*17 + u]

    const int t  = threadIdx.x;
    const int tx = t & 15;
    const int ty = (t >> 4) & 15;
    const int tz = t >> 8;
    const int bBase = blockIdx.x * 64;
    const int mBase = blockIdx.y * 64;

    // cp.async mappings: x = 1 op/thread (512 uint4/chunk), c = 2 ops/thread
    const int xq = t & 7,  xr = t >> 3;
    const int cq = t & 15, cr = t >> 4;
    const uint32_t* xsrc = g_xb + (size_t)(bBase + xr) * (DD / 2) + xq * 4;
    const uint32_t* csrc = g_cb + (size_t)(mBase + cr) * DD + cq * 4;

    uint32_t xd[2], cd[2];
    xd[0] = (uint32_t)__cvta_generic_to_shared(&xs[xr * 8 + xq]);
    xd[1] = xd[0] + 512 * 16;
    cd[0] = (uint32_t)__cvta_generic_to_shared(&cs[cr * 17 + cq]);
    cd[1] = cd[0] + 1088 * 16;

    auto load_chunk = [&](int ck) {
        int s = ck & 1;
        cp16(xd[s], xsrc + ck * 32);
        const uint32_t* cp = csrc + ck * 64;
        cp16(cd[s],                cp);
        cp16(cd[s] + 32 * 17 * 16, cp + 32 * DD);
        asm volatile("cp.async.commit_group;");
    };

    load_chunk(0);
    load_chunk(1);

    const uint32_t ONE2 = 0x3F803F80u;   // bf16x2 {1.0, 1.0}
    __nv_bfloat162 prod[4][4];
    float acc[4][4];
#pragma unroll
    for (int i = 0; i < 4; i++)
#pragma unroll
        for (int jm = 0; jm < 4; jm++) { prod[i][jm] = asbf2(ONE2); acc[i][jm] = 0.0f; }

    for (int ck = 0; ck < NCHUNK; ck++) {
        asm volatile("cp.async.wait_group 1;");
        __syncthreads();
        const int s = ck & 1;
        const uint4* xb = xs + s * 512  + ty * 8  + tz * 4;
        const uint4* cb = cs + s * 1088 + tx * 17 + tz * 8;
#pragma unroll
        for (int jq = 0; jq < 4; jq++) {          // 8 d per jq (per tz half)
            uint4 xv[4];
#pragma unroll
            for (int i = 0; i < 4; i++) xv[i] = xb[i * 128 + jq];
#pragma unroll
            for (int jm = 0; jm < 4; jm++) {
                uint4 cu0 = cb[jm * 272 + jq * 2];
                uint4 cu1 = cb[jm * 272 + jq * 2 + 1];
#pragma unroll
                for (int i = 0; i < 4; i++) {
                    __nv_bfloat162 l0 = __hfma2(asbf2(cu0.x), asbf2(xv[i].x), asbf2(cu0.y));
                    __nv_bfloat162 l1 = __hfma2(asbf2(cu0.z), asbf2(xv[i].y), asbf2(cu0.w));
                    __nv_bfloat162 l2 = __hfma2(asbf2(cu1.x), asbf2(xv[i].z), asbf2(cu1.y));
                    __nv_bfloat162 l3 = __hfma2(asbf2(cu1.z), asbf2(xv[i].w), asbf2(cu1.w));
                    __nv_bfloat162 m01 = __hmul2(l0, l1);
                    __nv_bfloat162 m23 = __hmul2(l2, l3);
                    prod[i][jm] = __hmul2(prod[i][jm], __hmul2(m01, m23));
                }
            }
        }
        __syncthreads();
        if (ck + 2 < NCHUNK) load_chunk(ck + 2);
        else asm volatile("cp.async.commit_group;");
        // merge: this chunk-half contributed 32 d per accumulator
#pragma unroll
        for (int i = 0; i < 4; i++)
#pragma unroll
            for (int jm = 0; jm < 4; jm++) {
                uint32_t u = asu32(prod[i][jm]);
                float hi = __uint_as_float(u & 0xFFFF0000u);
                float lo = __uint_as_float(u << 16);
                acc[i][jm] += __log2f(hi * lo);
                prod[i][jm] = asbf2(ONE2);
            }
    }

    asm volatile("cp.async.wait_group 0;");
    __syncthreads();
    // combine tz halves through smem (stride 17 floats to dodge bank conflicts)
    float* sh = (float*)sm;
    const int tid256 = t & 255;
    if (tz == 1) {
#pragma unroll
        for (int i = 0; i < 4; i++)
#pragma unroll
            for (int jm = 0; jm < 4; jm++)
                sh[tid256 * 17 + i * 4 + jm] = acc[i][jm];
    }
    __syncthreads();
    if (tz == 0) {
#pragma unroll
        for (int i = 0; i < 4; i++)
#pragma unroll
            for (int jm = 0; jm < 4; jm++) {
                float a = acc[i][jm] + sh[tid256 * 17 + i * 4 + jm];
                g_comp[(size_t)(bBase + ty + 16 * i) * MM + (mBase + tx + 16 * jm)] = a;
            }
    }
}

// ---------------------------------------------------------------------------
// Reduce: per-batch logsumexp over 256 components (one warp per batch).
// comp_ll = ln2*(acc2 - 1024) + logw   [undoes the 2^1024 scaling]
// ---------------------------------------------------------------------------
__global__ void reduce_kernel(float* __restrict__ out) {
    const float LN2 = 0.69314718055994531f;
    int warp = threadIdx.x >> 5;
    int lane = threadIdx.x & 31;
    int b = blockIdx.x * 8 + warp;
    const float4* cp4 = reinterpret_cast<const float4*>(g_comp + (size_t)b * MM);
    const float4* lw4 = reinterpret_cast<const float4*>(g_logw);
    float v[8];
    float mx = -1e30f;
#pragma unroll
    for (int k = 0; k < 2; k++) {
        float4 c = cp4[lane * 2 + k];
        float4 l = lw4[lane * 2 + k];
        v[k*4+0] = (c.x - 1024.0f) * LN2 + l.x;
        v[k*4+1] = (c.y - 1024.0f) * LN2 + l.y;
        v[k*4+2] = (c.z - 1024.0f) * LN2 + l.z;
        v[k*4+3] = (c.w - 1024.0f) * LN2 + l.w;
#pragma unroll
        for (int j = 0; j < 4; j++) mx = fmaxf(mx, v[k*4+j]);
    }
#pragma unroll
    for (int o = 16; o > 0; o >>= 1) mx = fmaxf(mx, __shfl_xor_sync(0xFFFFFFFFu, mx, o));
    float s = 0.0f;
#pragma unroll
    for (int k = 0; k < 8; k++) s += __expf(v[k] - mx);
#pragma unroll
    for (int o = 16; o > 0; o >>= 1) s += __shfl_xor_sync(0xFFFFFFFFu, s, o);
    if (lane == 0) out[b] = mx + __logf(s);
}

extern "C" void kernel_launch(void* const* d_in, const int* in_sizes, int n_in,
                              void* d_out, int out_size) {
    const float* x = nullptr;
    const float* W = nullptr;
    const float* P = nullptr;
    for (int i = 0; i < n_in; i++) {
        if      (in_sizes[i] == BBATCH * DD) x = (const float*)d_in[i];
        else if (in_sizes[i] == MM)          W = (const float*)d_in[i];
        else if (in_sizes[i] == MM * DD)     P = (const float*)d_in[i];
    }

    prep_kernel<<<2561, 256>>>(x, P, W);

    const int SMEM = 1024 * 16 + 2176 * 16;               // 51200 bytes
    cudaFuncSetAttribute(main_kernel, cudaFuncAttributeMaxDynamicSharedMemorySize, SMEM);
    dim3 grid(BBATCH / 64, MM / 64);
    main_kernel<<<grid, 512, SMEM>>>();

    reduce_kernel<<<BBATCH / 8, 256>>>((float*)d_out);
}